// round 4
// baseline (speedup 1.0000x reference)
#include <cuda_runtime.h>
#include <math.h>

#define BB 128
#define DD 128
#define QQ 256
#define LL 1024
#define TEMP 4.0f

#define QUERY_ELEMS ((size_t)BB * DD * QQ)   // 4,194,304
#define CTX_ELEMS   ((size_t)BB * DD * LL)   // 16,777,216
#define WC_ELEMS    ((size_t)BB * DD * QQ)   // 4,194,304
#define AMAP_ELEMS  ((size_t)BB * QQ * LL)   // 33,554,432

// scratch (static device globals; no runtime alloc). 16B-aligned for float4.
__device__ __align__(16) float g_attn_q[(size_t)BB * LL * QQ];   // 134 MB
__device__ __align__(16) float g_scratch_amap[AMAP_ELEMS];       // fallback
__device__ __align__(16) float g_scratch_wc[WC_ELEMS];           // fallback

// ---------------------------------------------------------------------------
// Kernel 1: scores = ctx^T @ query per batch, fused softmax over Q (axis -1).
// grid (L/64, B), block 256. dyn smem: As[128][64] + Bs[128][256] = 160 KB.
// Output tile per CTA: 64 (l) x 256 (q).
// ---------------------------------------------------------------------------
__global__ void k1_scores_softmaxq(const float* __restrict__ query,
                                   const float* __restrict__ ctx) {
    extern __shared__ float sm1[];
    float* As = sm1;               // [128][64]  As[k][m] = ctx[b, k, l0+m]
    float* Bs = sm1 + 128 * 64;    // [128][256] Bs[k][n] = query[b, k, n]

    const int tid = threadIdx.x;
    const int b   = blockIdx.y;
    const int l0  = blockIdx.x * 64;

    const float* ctxb = ctx + (size_t)b * DD * LL;
    const float* qb   = query + (size_t)b * DD * QQ;

    {
        float4* As4 = (float4*)As;
        #pragma unroll
        for (int r = 0; r < 8; r++) {         // 2048 float4 = 128x64 floats
            int idx = r * 256 + tid;
            int k = idx >> 4;                 // 16 float4 per 64-float row
            int f = idx & 15;
            As4[idx] = *(const float4*)(ctxb + (size_t)k * LL + l0 + f * 4);
        }
        const float4* q4  = (const float4*)qb;
        float4*       Bs4 = (float4*)Bs;
        #pragma unroll
        for (int r = 0; r < 32; r++) {        // 8192 float4 = 128x256 floats
            Bs4[r * 256 + tid] = q4[r * 256 + tid];
        }
    }
    __syncthreads();

    const int tm = tid >> 5;   // warp id 0..7 : 8 l-rows each
    const int tn = tid & 31;   // lane: cols tn*4..+3 and 128+tn*4..+3

    float acc[8][8];
    #pragma unroll
    for (int i = 0; i < 8; i++)
        #pragma unroll
        for (int j = 0; j < 8; j++) acc[i][j] = 0.0f;

    #pragma unroll 2
    for (int k = 0; k < 128; k++) {
        float4 a0 = *(const float4*)(As + k * 64 + tm * 8);
        float4 a1 = *(const float4*)(As + k * 64 + tm * 8 + 4);
        float4 b0 = *(const float4*)(Bs + k * 256 + tn * 4);
        float4 b1 = *(const float4*)(Bs + k * 256 + 128 + tn * 4);
        float a[8] = {a0.x, a0.y, a0.z, a0.w, a1.x, a1.y, a1.z, a1.w};
        float bv[8] = {b0.x, b0.y, b0.z, b0.w, b1.x, b1.y, b1.z, b1.w};
        #pragma unroll
        for (int i = 0; i < 8; i++)
            #pragma unroll
            for (int j = 0; j < 8; j++)
                acc[i][j] = fmaf(a[i], bv[j], acc[i][j]);
    }

    const size_t outbase = ((size_t)b * LL + l0 + tm * 8) * QQ;
    #pragma unroll
    for (int i = 0; i < 8; i++) {
        float m = acc[i][0];
        #pragma unroll
        for (int j = 1; j < 8; j++) m = fmaxf(m, acc[i][j]);
        #pragma unroll
        for (int o = 16; o; o >>= 1) m = fmaxf(m, __shfl_xor_sync(0xffffffffu, m, o));

        float e[8];
        float s = 0.0f;
        #pragma unroll
        for (int j = 0; j < 8; j++) { e[j] = __expf(acc[i][j] - m); s += e[j]; }
        #pragma unroll
        for (int o = 16; o; o >>= 1) s += __shfl_xor_sync(0xffffffffu, s, o);
        float inv = 1.0f / s;

        float4 w0 = make_float4(e[0] * inv, e[1] * inv, e[2] * inv, e[3] * inv);
        float4 w1 = make_float4(e[4] * inv, e[5] * inv, e[6] * inv, e[7] * inv);
        *(float4*)(g_attn_q + outbase + (size_t)i * QQ + tn * 4)        = w0;
        *(float4*)(g_attn_q + outbase + (size_t)i * QQ + 128 + tn * 4) = w1;
    }
}

// ---------------------------------------------------------------------------
// Kernel 3: attn_c[b,q,l] = softmax_l(TEMP * attn_q[b,l,q]).
// grid (Q/32, B), block 1024. smem: 32 x 1025 transpose tile.
// ---------------------------------------------------------------------------
__global__ void k3_softmax_l(float* __restrict__ amap) {
    extern __shared__ float sm3[];

    const int tid  = threadIdx.x;
    const int b    = blockIdx.y;
    const int q0   = blockIdx.x * 32;
    const int w    = tid >> 5;
    const int lane = tid & 31;

    const float* src = g_attn_q + (size_t)b * LL * QQ + q0;
    #pragma unroll
    for (int i = 0; i < 32; i++) {
        int l = i * 32 + w;
        sm3[lane * 1025 + l] = src[(size_t)l * QQ + lane];
    }
    __syncthreads();

    const float* row = sm3 + w * 1025;
    float e[32];
    float mx = -1e30f;
    #pragma unroll
    for (int i = 0; i < 32; i++) {
        float v = TEMP * row[lane + 32 * i];
        e[i] = v;
        mx = fmaxf(mx, v);
    }
    #pragma unroll
    for (int o = 16; o; o >>= 1) mx = fmaxf(mx, __shfl_xor_sync(0xffffffffu, mx, o));

    float s = 0.0f;
    #pragma unroll
    for (int i = 0; i < 32; i++) { e[i] = __expf(e[i] - mx); s += e[i]; }
    #pragma unroll
    for (int o = 16; o; o >>= 1) s += __shfl_xor_sync(0xffffffffu, s, o);
    float inv = 1.0f / s;

    float* dst = amap + ((size_t)b * QQ + q0 + w) * LL;
    #pragma unroll
    for (int i = 0; i < 32; i++) dst[lane + 32 * i] = e[i] * inv;
}

// ---------------------------------------------------------------------------
// Kernel 4: weighted_context[b,d,q] = sum_l ctx[b,d,l] * attn_c[b,q,l].
// GEMM per CTA: M=128 (d) x N=128 (q), K=1024 (l) chunked by 32.
// grid (2, B), block 256, 8x8 per thread.
// Thread (tm,tn): rows {tm*4..+3, 64+tm*4..+3}, cols {tn*4..+3, 64+tn*4..+3}.
// ---------------------------------------------------------------------------
__global__ void k4_weighted(const float* __restrict__ ctx,
                            const float* __restrict__ amap,
                            float* __restrict__ wc) {
    extern __shared__ float sm4[];
    float* As = sm4;               // [128][32]  As[d][lk]
    float* Bs = sm4 + 128 * 32;    // [32][257]  Bs[lk][n], n in [0,128)

    const int tid = threadIdx.x;
    const int b   = blockIdx.y;
    const int n0  = blockIdx.x * 128;

    const float* ctxb = ctx + (size_t)b * DD * LL;
    const float* mb   = amap + ((size_t)b * QQ + n0) * LL;

    const int tm = tid >> 4;   // 0..15
    const int tn = tid & 15;   // 0..15

    float acc[8][8];
    #pragma unroll
    for (int i = 0; i < 8; i++)
        #pragma unroll
        for (int j = 0; j < 8; j++) acc[i][j] = 0.0f;

    for (int kc = 0; kc < 32; kc++) {
        const int l0 = kc * 32;
        __syncthreads();

        // A: [128 d][32 lk] = 1024 float4, direct copy.
        {
            float4* As4 = (float4*)As;
            #pragma unroll
            for (int r = 0; r < 4; r++) {
                int idx = r * 256 + tid;   // 0..1023
                int d = idx >> 3;          // 8 float4 per 32-float row
                int f = idx & 7;
                As4[idx] = *(const float4*)(ctxb + (size_t)d * LL + l0 + f * 4);
            }
        }
        // B: [128 n][32 lk] = 1024 float4 sources, transposed into [lk][n].
        {
            #pragma unroll
            for (int r = 0; r < 4; r++) {
                int idx = r * 256 + tid;   // 0..1023
                int n = idx >> 3;          // 0..127
                int f = idx & 7;
                float4 v = *(const float4*)(mb + (size_t)n * LL + l0 + f * 4);
                Bs[(f * 4 + 0) * 257 + n] = v.x;
                Bs[(f * 4 + 1) * 257 + n] = v.y;
                Bs[(f * 4 + 2) * 257 + n] = v.z;
                Bs[(f * 4 + 3) * 257 + n] = v.w;
            }
        }
        __syncthreads();

        #pragma unroll 4
        for (int k = 0; k < 32; k++) {
            float a[8], bv[8];
            #pragma unroll
            for (int i = 0; i < 4; i++) {
                a[i]     = As[(tm * 4 + i) * 32 + k];
                a[4 + i] = As[(64 + tm * 4 + i) * 32 + k];
            }
            #pragma unroll
            for (int j = 0; j < 4; j++) {
                bv[j]     = Bs[k * 257 + tn * 4 + j];
                bv[4 + j] = Bs[k * 257 + 64 + tn * 4 + j];
            }
            #pragma unroll
            for (int i = 0; i < 8; i++)
                #pragma unroll
                for (int j = 0; j < 8; j++)
                    acc[i][j] = fmaf(a[i], bv[j], acc[i][j]);
        }
    }

    float* outb = wc + (size_t)b * DD * QQ;
    #pragma unroll
    for (int i = 0; i < 4; i++) {
        int d1 = tm * 4 + i;
        int d2 = 64 + tm * 4 + i;
        float4 r0 = make_float4(acc[i][0], acc[i][1], acc[i][2], acc[i][3]);
        float4 r1 = make_float4(acc[i][4], acc[i][5], acc[i][6], acc[i][7]);
        float4 r2 = make_float4(acc[4 + i][0], acc[4 + i][1], acc[4 + i][2], acc[4 + i][3]);
        float4 r3 = make_float4(acc[4 + i][4], acc[4 + i][5], acc[4 + i][6], acc[4 + i][7]);
        *(float4*)(outb + (size_t)d1 * QQ + n0 + tn * 4)       = r0;
        *(float4*)(outb + (size_t)d1 * QQ + n0 + 64 + tn * 4)  = r1;
        *(float4*)(outb + (size_t)d2 * QQ + n0 + tn * 4)       = r2;
        *(float4*)(outb + (size_t)d2 * QQ + n0 + 64 + tn * 4)  = r3;
    }
}

// ---------------------------------------------------------------------------
extern "C" void kernel_launch(void* const* d_in, const int* in_sizes, int n_in,
                              void* d_out, int out_size) {
    // Select inputs by element count (robust to metadata ordering).
    const float* query;
    const float* ctx;
    if ((size_t)in_sizes[0] == QUERY_ELEMS) {
        query = (const float*)d_in[0];
        ctx   = (const float*)d_in[1];
    } else {
        query = (const float*)d_in[1];
        ctx   = (const float*)d_in[0];
    }

    // Output layout: branch on out_size so we never write past d_out.
    float* wc;
    float* amap;
    void* sym;
    if ((size_t)out_size >= WC_ELEMS + AMAP_ELEMS) {
        wc   = (float*)d_out;
        amap = (float*)d_out + WC_ELEMS;
    } else if ((size_t)out_size == WC_ELEMS) {
        wc = (float*)d_out;
        cudaGetSymbolAddress(&sym, g_scratch_amap);
        amap = (float*)sym;
    } else {
        cudaGetSymbolAddress(&sym, g_scratch_wc);
        wc = (float*)sym;
        amap = (float*)d_out;
    }

    const int SMEM_K1 = (128 * 64 + 128 * 256) * sizeof(float);   // 160 KB
    const int SMEM_K3 = (32 * 1025) * sizeof(float);              // 131.2 KB
    const int SMEM_K4 = (128 * 32 + 32 * 257) * sizeof(float);    // 49.3 KB

    cudaFuncSetAttribute(k1_scores_softmaxq,
                         cudaFuncAttributeMaxDynamicSharedMemorySize, SMEM_K1);
    cudaFuncSetAttribute(k3_softmax_l,
                         cudaFuncAttributeMaxDynamicSharedMemorySize, SMEM_K3);
    cudaFuncSetAttribute(k4_weighted,
                         cudaFuncAttributeMaxDynamicSharedMemorySize, SMEM_K4);

    k1_scores_softmaxq<<<dim3(LL / 64, BB), 256, SMEM_K1>>>(query, ctx);
    k3_softmax_l<<<dim3(QQ / 32, BB), 1024, SMEM_K3>>>(amap);
    k4_weighted<<<dim3(2, BB), 256, SMEM_K4>>>(ctx, amap, wc);
}

// round 6
// speedup vs baseline: 1.2061x; 1.2061x over previous
#include <cuda_runtime.h>
#include <cuda_bf16.h>
#include <cstdint>
#include <math.h>

#define BB 128
#define DD 128
#define QQ 256
#define LL 1024
#define TEMP 4.0f

#define QUERY_ELEMS ((size_t)BB * DD * QQ)   // 4,194,304
#define WC_ELEMS    ((size_t)BB * DD * QQ)   // 4,194,304
#define AMAP_ELEMS  ((size_t)BB * QQ * LL)   // 33,554,432

// scratch (static device globals; no runtime alloc). 16B-aligned for float4.
__device__ __align__(16) float g_attn_q[(size_t)BB * LL * QQ];   // 134 MB
__device__ __align__(16) float g_scratch_amap[AMAP_ELEMS];       // fallback
__device__ __align__(16) float g_scratch_wc[WC_ELEMS];           // fallback

// ============================ helpers ======================================
__device__ __forceinline__ uint32_t smem_u32(const void* p) {
    uint32_t a;
    asm("{ .reg .u64 t; cvta.to.shared.u64 t, %1; cvt.u32.u64 %0, t; }"
        : "=r"(a) : "l"(p));
    return a;
}
__device__ __forceinline__ uint32_t pack2bf(float x, float y) {
    __nv_bfloat162 h = __floats2bfloat162_rn(x, y);
    return *(uint32_t*)&h;
}
// split v into bf16 hi pair + bf16 residual pair (packed b32 each)
__device__ __forceinline__ void split2(float x, float y,
                                       uint32_t& hi, uint32_t& lo) {
    __nv_bfloat16 hx = __float2bfloat16_rn(x);
    __nv_bfloat16 hy = __float2bfloat16_rn(y);
    float rx = x - __bfloat162float(hx);
    float ry = y - __bfloat162float(hy);
    __nv_bfloat162 h2; h2.x = hx; h2.y = hy;
    hi = *(uint32_t*)&h2;
    lo = pack2bf(rx, ry);
}
#define LDMATRIX_X4(r0, r1, r2, r3, addr) \
    asm volatile("ldmatrix.sync.aligned.m8n8.x4.shared.b16 {%0,%1,%2,%3}, [%4];" \
                 : "=r"(r0), "=r"(r1), "=r"(r2), "=r"(r3) : "r"(addr))
#define MMA_BF16(c, a0, a1, a2, a3, b0, b1) \
    asm volatile("mma.sync.aligned.m16n8k16.row.col.f32.bf16.bf16.f32 " \
                 "{%0,%1,%2,%3}, {%4,%5,%6,%7}, {%8,%9}, {%0,%1,%2,%3};" \
                 : "+f"((c)[0]), "+f"((c)[1]), "+f"((c)[2]), "+f"((c)[3]) \
                 : "r"(a0), "r"(a1), "r"(a2), "r"(a3), "r"(b0), "r"(b1))

// ---------------------------------------------------------------------------
// Kernel 1: scores = ctx^T @ query per batch, fused softmax over Q (axis -1).
// grid (L/64, B), block 256. dyn smem 160 KB. (unchanged)
// ---------------------------------------------------------------------------
__global__ void k1_scores_softmaxq(const float* __restrict__ query,
                                   const float* __restrict__ ctx) {
    extern __shared__ float sm1[];
    float* As = sm1;               // [128][64]
    float* Bs = sm1 + 128 * 64;    // [128][256]

    const int tid = threadIdx.x;
    const int b   = blockIdx.y;
    const int l0  = blockIdx.x * 64;

    const float* ctxb = ctx + (size_t)b * DD * LL;
    const float* qb   = query + (size_t)b * DD * QQ;

    {
        float4* As4 = (float4*)As;
        #pragma unroll
        for (int r = 0; r < 8; r++) {
            int idx = r * 256 + tid;
            int k = idx >> 4;
            int f = idx & 15;
            As4[idx] = *(const float4*)(ctxb + (size_t)k * LL + l0 + f * 4);
        }
        const float4* q4  = (const float4*)qb;
        float4*       Bs4 = (float4*)Bs;
        #pragma unroll
        for (int r = 0; r < 32; r++) Bs4[r * 256 + tid] = q4[r * 256 + tid];
    }
    __syncthreads();

    const int tm = tid >> 5;
    const int tn = tid & 31;

    float acc[8][8];
    #pragma unroll
    for (int i = 0; i < 8; i++)
        #pragma unroll
        for (int j = 0; j < 8; j++) acc[i][j] = 0.0f;

    #pragma unroll 2
    for (int k = 0; k < 128; k++) {
        float4 a0 = *(const float4*)(As + k * 64 + tm * 8);
        float4 a1 = *(const float4*)(As + k * 64 + tm * 8 + 4);
        float4 b0 = *(const float4*)(Bs + k * 256 + tn * 4);
        float4 b1 = *(const float4*)(Bs + k * 256 + 128 + tn * 4);
        float a[8]  = {a0.x, a0.y, a0.z, a0.w, a1.x, a1.y, a1.z, a1.w};
        float bv[8] = {b0.x, b0.y, b0.z, b0.w, b1.x, b1.y, b1.z, b1.w};
        #pragma unroll
        for (int i = 0; i < 8; i++)
            #pragma unroll
            for (int j = 0; j < 8; j++)
                acc[i][j] = fmaf(a[i], bv[j], acc[i][j]);
    }

    const size_t outbase = ((size_t)b * LL + l0 + tm * 8) * QQ;
    #pragma unroll
    for (int i = 0; i < 8; i++) {
        float m = acc[i][0];
        #pragma unroll
        for (int j = 1; j < 8; j++) m = fmaxf(m, acc[i][j]);
        #pragma unroll
        for (int o = 16; o; o >>= 1) m = fmaxf(m, __shfl_xor_sync(0xffffffffu, m, o));

        float e[8];
        float s = 0.0f;
        #pragma unroll
        for (int j = 0; j < 8; j++) { e[j] = __expf(acc[i][j] - m); s += e[j]; }
        #pragma unroll
        for (int o = 16; o; o >>= 1) s += __shfl_xor_sync(0xffffffffu, s, o);
        float inv = 1.0f / s;

        float4 w0 = make_float4(e[0] * inv, e[1] * inv, e[2] * inv, e[3] * inv);
        float4 w1 = make_float4(e[4] * inv, e[5] * inv, e[6] * inv, e[7] * inv);
        *(float4*)(g_attn_q + outbase + (size_t)i * QQ + tn * 4)        = w0;
        *(float4*)(g_attn_q + outbase + (size_t)i * QQ + 128 + tn * 4) = w1;
    }
}

// ---------------------------------------------------------------------------
// Kernel 3: attn_c[b,q,l] = softmax_l(TEMP * attn_q[b,l,q]). (unchanged)
// ---------------------------------------------------------------------------
__global__ void k3_softmax_l(float* __restrict__ amap) {
    extern __shared__ float sm3[];

    const int tid  = threadIdx.x;
    const int b    = blockIdx.y;
    const int q0   = blockIdx.x * 32;
    const int w    = tid >> 5;
    const int lane = tid & 31;

    const float* src = g_attn_q + (size_t)b * LL * QQ + q0;
    #pragma unroll
    for (int i = 0; i < 32; i++) {
        int l = i * 32 + w;
        sm3[lane * 1025 + l] = src[(size_t)l * QQ + lane];
    }
    __syncthreads();

    const float* row = sm3 + w * 1025;
    float e[32];
    float mx = -1e30f;
    #pragma unroll
    for (int i = 0; i < 32; i++) {
        float v = TEMP * row[lane + 32 * i];
        e[i] = v;
        mx = fmaxf(mx, v);
    }
    #pragma unroll
    for (int o = 16; o; o >>= 1) mx = fmaxf(mx, __shfl_xor_sync(0xffffffffu, mx, o));

    float s = 0.0f;
    #pragma unroll
    for (int i = 0; i < 32; i++) { e[i] = __expf(e[i] - mx); s += e[i]; }
    #pragma unroll
    for (int o = 16; o; o >>= 1) s += __shfl_xor_sync(0xffffffffu, s, o);
    float inv = 1.0f / s;

    float* dst = amap + ((size_t)b * QQ + q0 + w) * LL;
    #pragma unroll
    for (int i = 0; i < 32; i++) dst[lane + 32 * i] = e[i] * inv;
}

// ---------------------------------------------------------------------------
// Kernel 4 (HMMA bf16 split): wc[b,d,q] = sum_l ctx[b,d,l] * attn_c[b,q,l].
// CTA tile: 64 d x 128 q, K=1024 chunked by 32. grid (4, B), block 256.
// 8 warps = 2(m) x 4(n); warp tile 32x32 = 2 m16-tiles x 4 n8-tiles.
// 3-pass split: D = hiA*hiB + hiA*loB + loA*hiB (error ~2^-18 per product).
// smem rows padded to 80B (5x16B, coprime 8 -> conflict-free ldmatrix).
// ---------------------------------------------------------------------------
#define KC    32
#define NCH   (LL / KC)            // 32
#define ROWU  20                   // u32 per smem row (16 used + 4 pad)
#define AHI_O 0
#define ALO_O (64 * ROWU)          // 1280
#define BHI_O (2 * 64 * ROWU)      // 2560
#define BLO_O (2 * 64 * ROWU + 128 * ROWU)  // 5120
#define SM4U  (2 * 64 * ROWU + 2 * 128 * ROWU)  // 7680 u32 = 30 KB

__global__ __launch_bounds__(256)
void k4_mma(const float* __restrict__ ctx,
            const float* __restrict__ amap,
            float* __restrict__ wc) {
    __shared__ __align__(16) uint32_t sm[SM4U];
    const uint32_t sb = smem_u32(sm);

    const int tid  = threadIdx.x;
    const int lane = tid & 31;
    const int wid  = tid >> 5;
    const int wm   = wid & 1;        // warp m: 0..1 (32 d each)
    const int wn   = wid >> 1;       // warp n: 0..3 (32 q each)

    const int b  = blockIdx.y;
    const int d0 = (blockIdx.x & 1) * 64;
    const int q0 = (blockIdx.x >> 1) * 128;

    const float* A  = ctx  + (size_t)b * DD * LL + (size_t)d0 * LL;
    const float* Bm = amap + ((size_t)b * QQ + q0) * LL;

    float acc[2][4][4];
    #pragma unroll
    for (int i = 0; i < 2; i++)
        #pragma unroll
        for (int j = 0; j < 4; j++)
            #pragma unroll
            for (int k = 0; k < 4; k++) acc[i][j][k] = 0.0f;

    // ldmatrix lane addresses (byte offsets within smem), constant across chunks
    const uint32_t a_row = wm * 32 + (lane & 15);
    const uint32_t a_col = (lane >> 4) * 16;                  // bytes
    const uint32_t b_rowbase = wn * 32 + ((lane >> 4) << 3) + (lane & 7);
    const uint32_t b_col = ((lane >> 3) & 1) * 16;            // bytes

    for (int c = 0; c < NCH; c++) {
        const int l0 = c * KC;

        // ---- fill: A 64x32 (2 float4/thread), B 128x32 (4 float4/thread) ----
        #pragma unroll
        for (int t = 0; t < 2; t++) {
            int idx = t * 256 + tid;          // 0..511
            int row = idx >> 3;
            int f   = idx & 7;
            float4 v = *(const float4*)(A + (size_t)row * LL + l0 + f * 4);
            uint32_t h0, l0p, h1, l1p;
            split2(v.x, v.y, h0, l0p);
            split2(v.z, v.w, h1, l1p);
            int o = row * ROWU + f * 2;
            sm[AHI_O + o] = h0; sm[AHI_O + o + 1] = h1;
            sm[ALO_O + o] = l0p; sm[ALO_O + o + 1] = l1p;
        }
        #pragma unroll
        for (int t = 0; t < 4; t++) {
            int idx = t * 256 + tid;          // 0..1023
            int row = idx >> 3;
            int f   = idx & 7;
            float4 v = *(const float4*)(Bm + (size_t)row * LL + l0 + f * 4);
            uint32_t h0, l0p, h1, l1p;
            split2(v.x, v.y, h0, l0p);
            split2(v.z, v.w, h1, l1p);
            int o = row * ROWU + f * 2;
            sm[BHI_O + o] = h0; sm[BHI_O + o + 1] = h1;
            sm[BLO_O + o] = l0p; sm[BLO_O + o + 1] = l1p;
        }
        __syncthreads();

        // ---- compute: 2 k16-steps ----
        #pragma unroll
        for (int ks = 0; ks < 2; ks++) {
            const uint32_t kbyte = ks * 32;

            uint32_t ah[2][4], al[2][4];
            #pragma unroll
            for (int mt = 0; mt < 2; mt++) {
                uint32_t addr = sb + 4 * (AHI_O + (a_row + mt * 16) * ROWU)
                              + kbyte + a_col;
                LDMATRIX_X4(ah[mt][0], ah[mt][1], ah[mt][2], ah[mt][3], addr);
                addr += 4 * (ALO_O - AHI_O);
                LDMATRIX_X4(al[mt][0], al[mt][1], al[mt][2], al[mt][3], addr);
            }
            uint32_t bh[4][2], bl[4][2];
            #pragma unroll
            for (int p = 0; p < 2; p++) {     // each x4 covers 2 n8-tiles
                uint32_t addr = sb + 4 * (BHI_O + (b_rowbase + p * 16) * ROWU)
                              + kbyte + b_col;
                LDMATRIX_X4(bh[p * 2][0], bh[p * 2][1],
                            bh[p * 2 + 1][0], bh[p * 2 + 1][1], addr);
                addr += 4 * (BLO_O - BHI_O);
                LDMATRIX_X4(bl[p * 2][0], bl[p * 2][1],
                            bl[p * 2 + 1][0], bl[p * 2 + 1][1], addr);
            }

            // pass 1: hiA * hiB
            #pragma unroll
            for (int mt = 0; mt < 2; mt++)
                #pragma unroll
                for (int nt = 0; nt < 4; nt++)
                    MMA_BF16(acc[mt][nt], ah[mt][0], ah[mt][1], ah[mt][2],
                             ah[mt][3], bh[nt][0], bh[nt][1]);
            // pass 2: hiA * loB
            #pragma unroll
            for (int mt = 0; mt < 2; mt++)
                #pragma unroll
                for (int nt = 0; nt < 4; nt++)
                    MMA_BF16(acc[mt][nt], ah[mt][0], ah[mt][1], ah[mt][2],
                             ah[mt][3], bl[nt][0], bl[nt][1]);
            // pass 3: loA * hiB
            #pragma unroll
            for (int mt = 0; mt < 2; mt++)
                #pragma unroll
                for (int nt = 0; nt < 4; nt++)
                    MMA_BF16(acc[mt][nt], al[mt][0], al[mt][1], al[mt][2],
                             al[mt][3], bh[nt][0], bh[nt][1]);
        }
        __syncthreads();
    }

    // ---- epilogue ----
    float* outb = wc + (size_t)b * DD * QQ;
    const int gid = lane >> 2;          // 0..7
    const int tig = lane & 3;           // 0..3
    #pragma unroll
    for (int mt = 0; mt < 2; mt++) {
        #pragma unroll
        for (int nt = 0; nt < 4; nt++) {
            int d = d0 + wm * 32 + mt * 16 + gid;
            int q = q0 + wn * 32 + nt * 8 + tig * 2;
            *(float2*)(outb + (size_t)d * QQ + q) =
                make_float2(acc[mt][nt][0], acc[mt][nt][1]);
            *(float2*)(outb + (size_t)(d + 8) * QQ + q) =
                make_float2(acc[mt][nt][2], acc[mt][nt][3]);
        }
    }
}

// ---------------------------------------------------------------------------
extern "C" void kernel_launch(void* const* d_in, const int* in_sizes, int n_in,
                              void* d_out, int out_size) {
    const float* query;
    const float* ctx;
    if ((size_t)in_sizes[0] == QUERY_ELEMS) {
        query = (const float*)d_in[0];
        ctx   = (const float*)d_in[1];
    } else {
        query = (const float*)d_in[1];
        ctx   = (const float*)d_in[0];
    }

    float* wc;
    float* amap;
    void* sym;
    if ((size_t)out_size >= WC_ELEMS + AMAP_ELEMS) {
        wc   = (float*)d_out;
        amap = (float*)d_out + WC_ELEMS;
    } else if ((size_t)out_size == WC_ELEMS) {
        wc = (float*)d_out;
        cudaGetSymbolAddress(&sym, g_scratch_amap);
        amap = (float*)sym;
    } else {
        cudaGetSymbolAddress(&sym, g_scratch_wc);
        wc = (float*)sym;
        amap = (float*)d_out;
    }

    const int SMEM_K1 = (128 * 64 + 128 * 256) * sizeof(float);   // 160 KB
    const int SMEM_K3 = (32 * 1025) * sizeof(float);              // 131.2 KB

    cudaFuncSetAttribute(k1_scores_softmaxq,
                         cudaFuncAttributeMaxDynamicSharedMemorySize, SMEM_K1);
    cudaFuncSetAttribute(k3_softmax_l,
                         cudaFuncAttributeMaxDynamicSharedMemorySize, SMEM_K3);

    k1_scores_softmaxq<<<dim3(LL / 64, BB), 256, SMEM_K1>>>(query, ctx);
    k3_softmax_l<<<dim3(QQ / 32, BB), 1024, SMEM_K3>>>(amap);
    k4_mma<<<dim3(4, BB), 256>>>(ctx, amap, wc);
}